// round 10
// baseline (speedup 1.0000x reference)
#include <cuda_runtime.h>
#include <cuda_fp16.h>
#include <cstdint>

#define N_CAND 65536
#define HID 1024
#define C_CH 256
#define HW 361

// ---------------- scratch ----------------
__device__ float g_b1eff[HID];
__device__ float g_P[2 * HW * HID];          // [go/to][pos][1024] fp32
__device__ int   g_go[N_CAND], g_to[N_CAND];
__device__ __half g_c16[N_CAND * 64];        // cand feats fp16 [m][64]
__device__ __half g_Wc16[HID * 64];          // W1c^T [n][64]
__device__ __half g_W216[HID * HID];         // W2^T  [n][1024]
__device__ __half g_h116[(size_t)N_CAND * HID];
__device__ float g_part[8 * N_CAND];

// ---------------- helpers ----------------
__device__ __forceinline__ uint32_t smem_u32(const void* p) {
    uint32_t a;
    asm("{ .reg .u64 t; cvta.to.shared.u64 t, %1; cvt.u32.u64 %0, t; }" : "=r"(a) : "l"(p));
    return a;
}
__device__ __forceinline__ void cp16(uint32_t dst, const void* src) {
    asm volatile("cp.async.cg.shared.global [%0], [%1], 16;" :: "r"(dst), "l"(src));
}
__device__ __forceinline__ void cp_commit() { asm volatile("cp.async.commit_group;" ::: "memory"); }
template<int N> __device__ __forceinline__ void cp_wait() {
    asm volatile("cp.async.wait_group %0;" :: "n"(N) : "memory");
}
__device__ __forceinline__ void ldsm4(uint32_t* r, uint32_t a) {
    asm volatile("ldmatrix.sync.aligned.m8n8.x4.shared.b16 {%0,%1,%2,%3}, [%4];"
                 : "=r"(r[0]), "=r"(r[1]), "=r"(r[2]), "=r"(r[3]) : "r"(a));
}
__device__ __forceinline__ void ldsm2(uint32_t* r, uint32_t a) {
    asm volatile("ldmatrix.sync.aligned.m8n8.x2.shared.b16 {%0,%1}, [%2];"
                 : "=r"(r[0]), "=r"(r[1]) : "r"(a));
}
__device__ __forceinline__ void mmaf16(float* c, const uint32_t* a, const uint32_t* b) {
    asm volatile("mma.sync.aligned.m16n8k16.row.col.f32.f16.f16.f32 "
                 "{%0,%1,%2,%3}, {%4,%5,%6,%7}, {%8,%9}, {%0,%1,%2,%3};"
                 : "+f"(c[0]), "+f"(c[1]), "+f"(c[2]), "+f"(c[3])
                 : "r"(a[0]), "r"(a[1]), "r"(a[2]), "r"(a[3]), "r"(b[0]), "r"(b[1]));
}
__device__ __forceinline__ uint32_t pack2h(__half a, __half b) {
    return ((uint32_t)__half_as_ushort(b) << 16) | __half_as_ushort(a);
}

// ---------------- prep kernels ----------------
__global__ void k_pool_b1(const float* __restrict__ pf,
                          const float* __restrict__ W1, const float* __restrict__ b1) {
    __shared__ float sgp[C_CH];
    int tid = threadIdx.x;
    const float* row = pf + (size_t)tid * HW;
    float s = 0.f;
    for (int p = 0; p < HW; p++) s += row[p];
    sgp[tid] = s / 361.0f;
    __syncthreads();
    int j = tid * 4;
    float4 acc = *(const float4*)&b1[j];
    for (int c = 0; c < C_CH; c++) {
        float g = sgp[c];
        float4 w = *(const float4*)&W1[(size_t)(512 + c) * HID + j];
        acc.x += g * w.x; acc.y += g * w.y; acc.z += g * w.z; acc.w += g * w.w;
    }
    *(float4*)&g_b1eff[j] = acc;
}

__global__ void k_ptab(const float* __restrict__ pf, const float* __restrict__ W1) {
    int p0 = blockIdx.x * 4;
    int gy = blockIdx.y;
    int n0 = blockIdx.z * 512 + threadIdx.x * 4;
    __shared__ float fs[4][C_CH];
    int tid = threadIdx.x;
    for (int idx = tid; idx < 4 * C_CH; idx += 128) {
        int r = idx >> 8, k = idx & 255;
        fs[r][k] = (p0 + r < HW) ? pf[(size_t)k * HW + p0 + r] : 0.f;
    }
    __syncthreads();
    float4 acc[4];
    #pragma unroll
    for (int r = 0; r < 4; r++) acc[r] = make_float4(0.f, 0.f, 0.f, 0.f);
    const float* Wb = W1 + (size_t)gy * C_CH * HID;
    for (int k = 0; k < C_CH; k++) {
        float4 w = *(const float4*)&Wb[(size_t)k * HID + n0];
        #pragma unroll
        for (int r = 0; r < 4; r++) {
            float f = fs[r][k];
            acc[r].x += f * w.x; acc[r].y += f * w.y;
            acc[r].z += f * w.z; acc[r].w += f * w.w;
        }
    }
    #pragma unroll
    for (int r = 0; r < 4; r++)
        if (p0 + r < HW)
            *(float4*)&g_P[((size_t)gy * HW + p0 + r) * HID + n0] = acc[r];
}

__global__ void k_cand(const float* __restrict__ cand) {
    int idx = blockIdx.x * 256 + threadIdx.x;
    float4 v = ((const float4*)cand)[idx];
    ((uint2*)g_c16)[idx] = make_uint2(pack2h(__float2half(v.x), __float2half(v.y)),
                                      pack2h(__float2half(v.z), __float2half(v.w)));
    if ((idx & 15) == 1) {
        int i = idx >> 4;
        int gr = min(max((int)(v.y * 18.0f), 0), 18);
        int gc = min(max((int)(v.z * 18.0f), 0), 18);
        int tr = min(max((int)(v.w * 18.0f), 0), 18);
        float f8 = cand[(size_t)i * 64 + 8];
        int tc = min(max((int)(f8 * 18.0f), 0), 18);
        g_go[i] = gr * 19 + gc;
        g_to[i] = tr * 19 + tc;
    }
}

__global__ void k_wcvt(const float* __restrict__ W2, const float* __restrict__ W1) {
    int tid = threadIdx.x;
    if (blockIdx.y < 32) {
        __shared__ float tile[32][33];
        int kt = blockIdx.y * 32, nt = blockIdx.x * 32;
        int tx = tid & 31, ty = tid >> 5;
        for (int r = ty; r < 32; r += 8)
            tile[r][tx] = W2[(size_t)(kt + r) * HID + nt + tx];
        __syncthreads();
        for (int r = ty; r < 32; r += 8)
            g_W216[(size_t)(nt + r) * HID + kt + tx] = __float2half(tile[tx][r]);
    } else {
        for (int t = 0; t < 8; t++) {
            int idx = blockIdx.x * 2048 + t * 256 + tid;
            int n = idx >> 6, k = idx & 63;
            g_Wc16[idx] = __float2half(W1[(size_t)(768 + k) * HID + n]);
        }
    }
}

// ---------------- GEMM1: CTA 128x128, 8 warps (2m x 4n), warp 64x32, K=64 ----------------
#define ROWB 80
#define G1_OA 0
#define G1_OB 10240
#define G1_STRIDE 20480
#define SMEM1 (2 * G1_STRIDE)

__global__ __launch_bounds__(256, 2)
void k_mma1() {
    extern __shared__ char smem[];
    const uint32_t sb = smem_u32(smem);
    const int tid = threadIdx.x;
    const int lane = tid & 31, wid = tid >> 5;
    const int wm = wid >> 2, wn = wid & 3;
    const int mBase = blockIdx.y * 128;
    const int nBase = blockIdx.x * 128;

    const int lrow = tid >> 1;
    const int lc = (tid & 1) * 2;
    const __half* aP = g_c16 + (size_t)(mBase + lrow) * 64 + lc * 8;
    const __half* bP = g_Wc16 + (size_t)(nBase + lrow) * 64 + lc * 8;
    const uint32_t sA = lrow * ROWB + lc * 16;

    auto load_chunk = [&](int chunk, int buf) {
        uint32_t st = sb + buf * G1_STRIDE;
        int k0 = chunk * 32;
        cp16(st + G1_OA + sA,      aP + k0);
        cp16(st + G1_OA + sA + 16, aP + k0 + 8);
        cp16(st + G1_OB + sA,      bP + k0);
        cp16(st + G1_OB + sA + 16, bP + k0 + 8);
        cp_commit();
    };
    load_chunk(0, 0);
    load_chunk(1, 1);

    float acc[4][4][4];
    #pragma unroll
    for (int i = 0; i < 4; i++)
        #pragma unroll
        for (int j = 0; j < 4; j++)
            #pragma unroll
            for (int q = 0; q < 4; q++) acc[i][j][q] = 0.f;

    const uint32_t aOff = (uint32_t)((wm * 64 + (lane & 15)) * ROWB + (lane >> 4) * 16);
    const uint32_t bOff = (uint32_t)((wn * 32 + (lane & 7)) * ROWB + ((lane >> 3) & 1) * 16);

    #pragma unroll
    for (int c = 0; c < 2; c++) {
        if (c == 0) cp_wait<1>(); else cp_wait<0>();
        __syncthreads();
        uint32_t st = sb + c * G1_STRIDE;
        #pragma unroll
        for (int kk = 0; kk < 2; kk++) {
            uint32_t a[4][4], b[4][2];
            #pragma unroll
            for (int i = 0; i < 4; i++)
                ldsm4(a[i], st + G1_OA + aOff + i * (16 * ROWB) + kk * 32);
            #pragma unroll
            for (int j = 0; j < 4; j++)
                ldsm2(b[j], st + G1_OB + bOff + j * (8 * ROWB) + kk * 32);
            #pragma unroll
            for (int i = 0; i < 4; i++)
                #pragma unroll
                for (int j = 0; j < 4; j++)
                    mmaf16(acc[i][j], a[i], b[j]);
        }
        __syncthreads();
    }

    int* sgo = (int*)smem;
    int* sto = (int*)(smem + 512);
    if (tid < 128) { sgo[tid] = g_go[mBase + tid]; sto[tid] = g_to[mBase + tid]; }
    __syncthreads();
    #pragma unroll
    for (int i = 0; i < 4; i++) {
        #pragma unroll
        for (int rr = 0; rr < 2; rr++) {
            int rl = wm * 64 + i * 16 + rr * 8 + (lane >> 2);
            size_t row = (size_t)(mBase + rl);
            const float* pg = g_P + (size_t)sgo[rl] * HID;
            const float* pt = g_P + (size_t)(HW + sto[rl]) * HID;
            #pragma unroll
            for (int j = 0; j < 4; j++) {
                int n = nBase + wn * 32 + j * 8 + 2 * (lane & 3);
                float v0 = acc[i][j][rr * 2 + 0] + pg[n] + pt[n] + g_b1eff[n];
                float v1 = acc[i][j][rr * 2 + 1] + pg[n + 1] + pt[n + 1] + g_b1eff[n + 1];
                v0 = fmaxf(v0, 0.f); v1 = fmaxf(v1, 0.f);
                *(uint32_t*)&g_h116[row * HID + n] = pack2h(__float2half(v0), __float2half(v1));
            }
        }
    }
}

// ---------------- GEMM2: CTA 128x256, 8 warps (2m x 4n), warp 64x64, 3-stage ----------------
#define G2_OA 0
#define G2_OB 10240
#define G2_STRIDE 30720
#define SMEM2 (3 * G2_STRIDE)

__global__ __launch_bounds__(256, 1)
void k_mma2(const float* __restrict__ b2, const float* __restrict__ w3) {
    extern __shared__ char smem[];
    const uint32_t sb = smem_u32(smem);
    const int tid = threadIdx.x;
    const int lane = tid & 31, wid = tid >> 5;
    const int wm = wid >> 2, wn = wid & 3;
    const int mBase = blockIdx.y * 128;
    const int nBase = blockIdx.x * 256;
    const int NC = 32;

    // loaders: A = 128 rows x 32 fp16 (2 threads/row); B = 256 rows x 32 fp16 (1 thread/row)
    const int arow = tid >> 1;
    const int ah = (tid & 1);                    // k-half of 32
    const __half* aP = g_h116 + (size_t)(mBase + arow) * HID + ah * 16;
    const __half* bP = g_W216 + (size_t)(nBase + tid) * HID;
    const uint32_t sAoff = arow * ROWB + ah * 32;
    const uint32_t sBoff = tid * ROWB;

    auto load_chunk = [&](int chunk, int buf) {
        uint32_t st = sb + buf * G2_STRIDE;
        int k0 = chunk * 32;
        cp16(st + G2_OA + sAoff,      aP + k0);
        cp16(st + G2_OA + sAoff + 16, aP + k0 + 8);
        cp16(st + G2_OB + sBoff,      bP + k0);
        cp16(st + G2_OB + sBoff + 16, bP + k0 + 8);
        cp16(st + G2_OB + sBoff + 32, bP + k0 + 16);
        cp16(st + G2_OB + sBoff + 48, bP + k0 + 24);
        cp_commit();
    };
    load_chunk(0, 0);
    load_chunk(1, 1);
    load_chunk(2, 2);

    float acc[4][8][4];
    #pragma unroll
    for (int i = 0; i < 4; i++)
        #pragma unroll
        for (int j = 0; j < 8; j++)
            #pragma unroll
            for (int q = 0; q < 4; q++) acc[i][j][q] = 0.f;

    const uint32_t aOff = (uint32_t)((wm * 64 + (lane & 15)) * ROWB + (lane >> 4) * 16);
    // ldsm.x4 over B: lanes0-7 -> n+(lane&7),kh0; 8-15 -> kh1; 16-23 -> n+8,kh0; 24-31 -> n+8,kh1
    const uint32_t bOff = (uint32_t)((wn * 64 + (lane & 7) + ((lane >> 4) << 3)) * ROWB
                                     + ((lane >> 3) & 1) * 16);

    int buf = 0;
    for (int c = 0; c < NC; c++) {
        if (NC - 1 - c >= 2) cp_wait<2>();
        else if (NC - 1 - c == 1) cp_wait<1>();
        else cp_wait<0>();
        __syncthreads();

        uint32_t st = sb + buf * G2_STRIDE;
        #pragma unroll
        for (int kk = 0; kk < 2; kk++) {
            uint32_t a[4][4], b[4][4];
            #pragma unroll
            for (int i = 0; i < 4; i++)
                ldsm4(a[i], st + G2_OA + aOff + i * (16 * ROWB) + kk * 32);
            #pragma unroll
            for (int j2 = 0; j2 < 4; j2++)
                ldsm4(b[j2], st + G2_OB + bOff + j2 * (16 * ROWB) + kk * 32);
            #pragma unroll
            for (int i = 0; i < 4; i++)
                #pragma unroll
                for (int j2 = 0; j2 < 4; j2++) {
                    mmaf16(acc[i][j2 * 2],     a[i], &b[j2][0]);
                    mmaf16(acc[i][j2 * 2 + 1], a[i], &b[j2][2]);
                }
        }
        __syncthreads();
        if (c + 3 < NC) load_chunk(c + 3, buf);
        buf = (buf + 1 == 3) ? 0 : buf + 1;
    }
    __syncthreads();

    float* red = (float*)smem;   // [4][128]
    #pragma unroll
    for (int i = 0; i < 4; i++) {
        float s0 = 0.f, s1 = 0.f;
        #pragma unroll
        for (int j = 0; j < 8; j++) {
            int n = nBase + wn * 64 + j * 8 + 2 * (lane & 3);
            float bb0 = b2[n], bb1 = b2[n + 1];
            float w0 = w3[n], w1 = w3[n + 1];
            s0 += fmaxf(acc[i][j][0] + bb0, 0.f) * w0 + fmaxf(acc[i][j][1] + bb1, 0.f) * w1;
            s1 += fmaxf(acc[i][j][2] + bb0, 0.f) * w0 + fmaxf(acc[i][j][3] + bb1, 0.f) * w1;
        }
        s0 += __shfl_xor_sync(0xffffffffu, s0, 1);
        s0 += __shfl_xor_sync(0xffffffffu, s0, 2);
        s1 += __shfl_xor_sync(0xffffffffu, s1, 1);
        s1 += __shfl_xor_sync(0xffffffffu, s1, 2);
        if ((lane & 3) == 0) {
            int rl = wm * 64 + i * 16 + (lane >> 2);
            red[wn * 128 + rl] = s0;
            red[wn * 128 + rl + 8] = s1;
        }
    }
    __syncthreads();
    if (tid < 128) {
        float s = red[tid] + red[128 + tid] + red[256 + tid] + red[384 + tid];
        g_part[(size_t)blockIdx.x * N_CAND + mBase + tid] = s;
    }
}

__global__ void k_reduce(const float* __restrict__ b3, float* __restrict__ out) {
    int n = blockIdx.x * 256 + threadIdx.x;
    float s = b3[0];
    #pragma unroll
    for (int t = 0; t < 4; t++) s += g_part[(size_t)t * N_CAND + n];
    out[n] = s;
}

// ---------------- launch ----------------
extern "C" void kernel_launch(void* const* d_in, const int* in_sizes, int n_in,
                              void* d_out, int out_size) {
    const float* pf   = (const float*)d_in[0];
    const float* cand = (const float*)d_in[1];
    const float* W1   = (const float*)d_in[2];
    const float* b1   = (const float*)d_in[3];
    const float* W2   = (const float*)d_in[4];
    const float* b2   = (const float*)d_in[5];
    const float* W3   = (const float*)d_in[6];
    const float* b3   = (const float*)d_in[7];
    float* out = (float*)d_out;

    k_pool_b1<<<1, 256>>>(pf, W1, b1);                     // 1
    k_ptab<<<dim3(91, 2, 2), 128>>>(pf, W1);               // 2
    k_cand<<<(N_CAND * 16) / 256, 256>>>(cand);            // 3
    k_wcvt<<<dim3(32, 33), 256>>>(W2, W1);                 // 4

    cudaFuncSetAttribute(k_mma1, cudaFuncAttributeMaxDynamicSharedMemorySize, SMEM1);
    cudaFuncSetAttribute(k_mma2, cudaFuncAttributeMaxDynamicSharedMemorySize, SMEM2);

    dim3 g1(HID / 128, N_CAND / 128);                      // (8, 512)
    k_mma1<<<g1, 256, SMEM1>>>();                          // 5
    dim3 g2(HID / 256, N_CAND / 128);                      // (4, 512)
    k_mma2<<<g2, 256, SMEM2>>>(b2, W3);                    // 6  <- ncu -s5 lands here
    k_reduce<<<N_CAND / 256, 256>>>(b3, out);              // 7
}

// round 12
// speedup vs baseline: 1.1860x; 1.1860x over previous
#include <cuda_runtime.h>
#include <cuda_fp16.h>
#include <cstdint>

#define N_CAND 65536
#define HID 1024
#define C_CH 256
#define HW 361

// ---------------- scratch ----------------
__device__ float g_b1eff[HID];
__device__ float g_P[2 * HW * HID];          // [go/to][pos][1024] fp32
__device__ int   g_go[N_CAND], g_to[N_CAND];
__device__ __half g_c16[N_CAND * 64];        // cand feats fp16 [m][64]
__device__ __half g_Wc16[HID * 64];          // W1c^T [n][64]
__device__ __half g_W216[HID * HID];         // W2^T  [n][1024]
__device__ __half g_h116[(size_t)N_CAND * HID];
__device__ float g_part[8 * N_CAND];

// ---------------- helpers ----------------
__device__ __forceinline__ uint32_t smem_u32(const void* p) {
    uint32_t a;
    asm("{ .reg .u64 t; cvta.to.shared.u64 t, %1; cvt.u32.u64 %0, t; }" : "=r"(a) : "l"(p));
    return a;
}
__device__ __forceinline__ void cp16(uint32_t dst, const void* src) {
    asm volatile("cp.async.cg.shared.global [%0], [%1], 16;" :: "r"(dst), "l"(src));
}
__device__ __forceinline__ void cp_commit() { asm volatile("cp.async.commit_group;" ::: "memory"); }
template<int N> __device__ __forceinline__ void cp_wait() {
    asm volatile("cp.async.wait_group %0;" :: "n"(N) : "memory");
}
__device__ __forceinline__ void ldsm4(uint32_t* r, uint32_t a) {
    asm volatile("ldmatrix.sync.aligned.m8n8.x4.shared.b16 {%0,%1,%2,%3}, [%4];"
                 : "=r"(r[0]), "=r"(r[1]), "=r"(r[2]), "=r"(r[3]) : "r"(a));
}
__device__ __forceinline__ void ldsm2(uint32_t* r, uint32_t a) {
    asm volatile("ldmatrix.sync.aligned.m8n8.x2.shared.b16 {%0,%1}, [%2];"
                 : "=r"(r[0]), "=r"(r[1]) : "r"(a));
}
__device__ __forceinline__ void mmaf16(float* c, const uint32_t* a, const uint32_t* b) {
    asm volatile("mma.sync.aligned.m16n8k16.row.col.f32.f16.f16.f32 "
                 "{%0,%1,%2,%3}, {%4,%5,%6,%7}, {%8,%9}, {%0,%1,%2,%3};"
                 : "+f"(c[0]), "+f"(c[1]), "+f"(c[2]), "+f"(c[3])
                 : "r"(a[0]), "r"(a[1]), "r"(a[2]), "r"(a[3]), "r"(b[0]), "r"(b[1]));
}
__device__ __forceinline__ uint32_t pack2h(__half a, __half b) {
    return ((uint32_t)__half_as_ushort(b) << 16) | __half_as_ushort(a);
}

// ---------------- prep kernels ----------------
__global__ void k_pool_b1(const float* __restrict__ pf,
                          const float* __restrict__ W1, const float* __restrict__ b1) {
    __shared__ float sgp[C_CH];
    int tid = threadIdx.x;
    const float* row = pf + (size_t)tid * HW;
    float s = 0.f;
    for (int p = 0; p < HW; p++) s += row[p];
    sgp[tid] = s / 361.0f;
    __syncthreads();
    int j = tid * 4;
    float4 acc = *(const float4*)&b1[j];
    for (int c = 0; c < C_CH; c++) {
        float g = sgp[c];
        float4 w = *(const float4*)&W1[(size_t)(512 + c) * HID + j];
        acc.x += g * w.x; acc.y += g * w.y; acc.z += g * w.z; acc.w += g * w.w;
    }
    *(float4*)&g_b1eff[j] = acc;
}

// P tables: P[gy][pos][n] = sum_k pf[k][pos] * W1[gy*256 + k][n]
// grid (91, 2, 2): 4 positions x gy x n-half; 256 threads x 2 n (float2)
__global__ void k_ptab(const float* __restrict__ pf, const float* __restrict__ W1) {
    int p0 = blockIdx.x * 4;
    int gy = blockIdx.y;
    int n0 = blockIdx.z * 512 + threadIdx.x * 2;
    __shared__ float fs[4][C_CH];
    int tid = threadIdx.x;
    for (int idx = tid; idx < 4 * C_CH; idx += 256) {
        int r = idx >> 8, k = idx & 255;
        fs[r][k] = (p0 + r < HW) ? pf[(size_t)k * HW + p0 + r] : 0.f;
    }
    __syncthreads();
    float2 acc[4];
    #pragma unroll
    for (int r = 0; r < 4; r++) acc[r] = make_float2(0.f, 0.f);
    const float* Wb = W1 + (size_t)gy * C_CH * HID;
    #pragma unroll 4
    for (int k = 0; k < C_CH; k++) {
        float2 w = *(const float2*)&Wb[(size_t)k * HID + n0];
        #pragma unroll
        for (int r = 0; r < 4; r++) {
            float f = fs[r][k];
            acc[r].x += f * w.x; acc[r].y += f * w.y;
        }
    }
    #pragma unroll
    for (int r = 0; r < 4; r++)
        if (p0 + r < HW)
            *(float2*)&g_P[((size_t)gy * HW + p0 + r) * HID + n0] = acc[r];
}

__global__ void k_cand(const float* __restrict__ cand) {
    int idx = blockIdx.x * 256 + threadIdx.x;
    float4 v = ((const float4*)cand)[idx];
    ((uint2*)g_c16)[idx] = make_uint2(pack2h(__float2half(v.x), __float2half(v.y)),
                                      pack2h(__float2half(v.z), __float2half(v.w)));
    if ((idx & 15) == 1) {
        int i = idx >> 4;
        int gr = min(max((int)(v.y * 18.0f), 0), 18);
        int gc = min(max((int)(v.z * 18.0f), 0), 18);
        int tr = min(max((int)(v.w * 18.0f), 0), 18);
        float f8 = cand[(size_t)i * 64 + 8];
        int tc = min(max((int)(f8 * 18.0f), 0), 18);
        g_go[i] = gr * 19 + gc;
        g_to[i] = tr * 19 + tc;
    }
}

__global__ void k_wcvt(const float* __restrict__ W2, const float* __restrict__ W1) {
    int tid = threadIdx.x;
    if (blockIdx.y < 32) {
        __shared__ float tile[32][33];
        int kt = blockIdx.y * 32, nt = blockIdx.x * 32;
        int tx = tid & 31, ty = tid >> 5;
        for (int r = ty; r < 32; r += 8)
            tile[r][tx] = W2[(size_t)(kt + r) * HID + nt + tx];
        __syncthreads();
        for (int r = ty; r < 32; r += 8)
            g_W216[(size_t)(nt + r) * HID + kt + tx] = __float2half(tile[tx][r]);
    } else {
        for (int t = 0; t < 8; t++) {
            int idx = blockIdx.x * 2048 + t * 256 + tid;
            int n = idx >> 6, k = idx & 63;
            g_Wc16[idx] = __float2half(W1[(size_t)(768 + k) * HID + n]);
        }
    }
}

// ---------------- GEMM1: CTA 128x128, 8 warps (2m x 4n), warp 64x32, K=64 ----------------
#define ROWB 80
#define G1_OA 0
#define G1_OB 10240
#define G1_STRIDE 20480
#define SMEM1 (2 * G1_STRIDE)

__global__ __launch_bounds__(256, 2)
void k_mma1() {
    extern __shared__ char smem[];
    const uint32_t sb = smem_u32(smem);
    const int tid = threadIdx.x;
    const int lane = tid & 31, wid = tid >> 5;
    const int wm = wid >> 2, wn = wid & 3;
    const int mBase = blockIdx.y * 128;
    const int nBase = blockIdx.x * 128;

    const int lrow = tid >> 1;
    const int lc = (tid & 1) * 2;
    const __half* aP = g_c16 + (size_t)(mBase + lrow) * 64 + lc * 8;
    const __half* bP = g_Wc16 + (size_t)(nBase + lrow) * 64 + lc * 8;
    const uint32_t sA = lrow * ROWB + lc * 16;

    auto load_chunk = [&](int chunk, int buf) {
        uint32_t st = sb + buf * G1_STRIDE;
        int k0 = chunk * 32;
        cp16(st + G1_OA + sA,      aP + k0);
        cp16(st + G1_OA + sA + 16, aP + k0 + 8);
        cp16(st + G1_OB + sA,      bP + k0);
        cp16(st + G1_OB + sA + 16, bP + k0 + 8);
        cp_commit();
    };
    load_chunk(0, 0);
    load_chunk(1, 1);

    float acc[4][4][4];
    #pragma unroll
    for (int i = 0; i < 4; i++)
        #pragma unroll
        for (int j = 0; j < 4; j++)
            #pragma unroll
            for (int q = 0; q < 4; q++) acc[i][j][q] = 0.f;

    const uint32_t aOff = (uint32_t)((wm * 64 + (lane & 15)) * ROWB + (lane >> 4) * 16);
    const uint32_t bOff = (uint32_t)((wn * 32 + (lane & 7)) * ROWB + ((lane >> 3) & 1) * 16);

    #pragma unroll
    for (int c = 0; c < 2; c++) {
        if (c == 0) cp_wait<1>(); else cp_wait<0>();
        __syncthreads();
        uint32_t st = sb + c * G1_STRIDE;
        #pragma unroll
        for (int kk = 0; kk < 2; kk++) {
            uint32_t a[4][4], b[4][2];
            #pragma unroll
            for (int i = 0; i < 4; i++)
                ldsm4(a[i], st + G1_OA + aOff + i * (16 * ROWB) + kk * 32);
            #pragma unroll
            for (int j = 0; j < 4; j++)
                ldsm2(b[j], st + G1_OB + bOff + j * (8 * ROWB) + kk * 32);
            #pragma unroll
            for (int i = 0; i < 4; i++)
                #pragma unroll
                for (int j = 0; j < 4; j++)
                    mmaf16(acc[i][j], a[i], b[j]);
        }
        __syncthreads();
    }

    int* sgo = (int*)smem;
    int* sto = (int*)(smem + 512);
    if (tid < 128) { sgo[tid] = g_go[mBase + tid]; sto[tid] = g_to[mBase + tid]; }
    __syncthreads();
    #pragma unroll
    for (int i = 0; i < 4; i++) {
        #pragma unroll
        for (int rr = 0; rr < 2; rr++) {
            int rl = wm * 64 + i * 16 + rr * 8 + (lane >> 2);
            size_t row = (size_t)(mBase + rl);
            const float* pg = g_P + (size_t)sgo[rl] * HID;
            const float* pt = g_P + (size_t)(HW + sto[rl]) * HID;
            #pragma unroll
            for (int j = 0; j < 4; j++) {
                int n = nBase + wn * 32 + j * 8 + 2 * (lane & 3);
                float2 pgv = *(const float2*)&pg[n];
                float2 ptv = *(const float2*)&pt[n];
                float2 bbv = *(const float2*)&g_b1eff[n];
                float v0 = acc[i][j][rr * 2 + 0] + pgv.x + ptv.x + bbv.x;
                float v1 = acc[i][j][rr * 2 + 1] + pgv.y + ptv.y + bbv.y;
                v0 = fmaxf(v0, 0.f); v1 = fmaxf(v1, 0.f);
                *(uint32_t*)&g_h116[row * HID + n] = pack2h(__float2half(v0), __float2half(v1));
            }
        }
    }
}

// ---------------- GEMM2: CTA 128x128, 8 warps (2m x 4n), warp 64x32, 3-stage ----------------
#define G2_OA 0
#define G2_OB 10240
#define G2_STRIDE 20480
#define SMEM2 (3 * G2_STRIDE)

__global__ __launch_bounds__(256, 2)
void k_mma2(const float* __restrict__ b2, const float* __restrict__ w3) {
    extern __shared__ char smem[];
    const uint32_t sb = smem_u32(smem);
    const int tid = threadIdx.x;
    const int lane = tid & 31, wid = tid >> 5;
    const int wm = wid >> 2, wn = wid & 3;
    const int mBase = blockIdx.y * 128;
    const int nBase = blockIdx.x * 128;
    const int NC = 32;

    const int lrow = tid >> 1;
    const int lc = (tid & 1) * 2;
    const __half* aP = g_h116 + (size_t)(mBase + lrow) * HID + lc * 8;
    const __half* bP = g_W216 + (size_t)(nBase + lrow) * HID + lc * 8;
    const uint32_t sA = lrow * ROWB + lc * 16;

    auto load_chunk = [&](int chunk, int buf) {
        uint32_t st = sb + buf * G2_STRIDE;
        int k0 = chunk * 32;
        cp16(st + G2_OA + sA,      aP + k0);
        cp16(st + G2_OA + sA + 16, aP + k0 + 8);
        cp16(st + G2_OB + sA,      bP + k0);
        cp16(st + G2_OB + sA + 16, bP + k0 + 8);
        cp_commit();
    };
    load_chunk(0, 0);
    load_chunk(1, 1);
    load_chunk(2, 2);

    float acc[4][4][4];
    #pragma unroll
    for (int i = 0; i < 4; i++)
        #pragma unroll
        for (int j = 0; j < 4; j++)
            #pragma unroll
            for (int q = 0; q < 4; q++) acc[i][j][q] = 0.f;

    const uint32_t aOff = (uint32_t)((wm * 64 + (lane & 15)) * ROWB + (lane >> 4) * 16);
    // B via ldsm.x4: lanes0-7 -> rows n0..7 (k-lo), 8-15 -> k-hi, 16-23 -> n8..15 (k-lo), 24-31 -> k-hi
    const uint32_t bOff = (uint32_t)((wn * 32 + (lane & 7) + ((lane >> 4) << 3)) * ROWB
                                     + ((lane >> 3) & 1) * 16);

    int buf = 0;
    for (int c = 0; c < NC; c++) {
        if (NC - 1 - c >= 2) cp_wait<2>();
        else if (NC - 1 - c == 1) cp_wait<1>();
        else cp_wait<0>();
        __syncthreads();

        uint32_t st = sb + buf * G2_STRIDE;
        #pragma unroll
        for (int kk = 0; kk < 2; kk++) {
            uint32_t a[4][4], b[2][4];
            #pragma unroll
            for (int i = 0; i < 4; i++)
                ldsm4(a[i], st + G2_OA + aOff + i * (16 * ROWB) + kk * 32);
            #pragma unroll
            for (int j2 = 0; j2 < 2; j2++)
                ldsm4(b[j2], st + G2_OB + bOff + j2 * (16 * ROWB) + kk * 32);
            #pragma unroll
            for (int i = 0; i < 4; i++)
                #pragma unroll
                for (int j2 = 0; j2 < 2; j2++) {
                    mmaf16(acc[i][j2 * 2],     a[i], &b[j2][0]);
                    mmaf16(acc[i][j2 * 2 + 1], a[i], &b[j2][2]);
                }
        }
        __syncthreads();
        if (c + 3 < NC) load_chunk(c + 3, buf);
        buf = (buf + 1 == 3) ? 0 : buf + 1;
    }
    __syncthreads();

    float* red = (float*)smem;   // [4][128]
    #pragma unroll
    for (int i = 0; i < 4; i++) {
        float s0 = 0.f, s1 = 0.f;
        #pragma unroll
        for (int j = 0; j < 4; j++) {
            int n = nBase + wn * 32 + j * 8 + 2 * (lane & 3);
            float2 bb = *(const float2*)&b2[n];
            float2 ww = *(const float2*)&w3[n];
            s0 += fmaxf(acc[i][j][0] + bb.x, 0.f) * ww.x + fmaxf(acc[i][j][1] + bb.y, 0.f) * ww.y;
            s1 += fmaxf(acc[i][j][2] + bb.x, 0.f) * ww.x + fmaxf(acc[i][j][3] + bb.y, 0.f) * ww.y;
        }
        s0 += __shfl_xor_sync(0xffffffffu, s0, 1);
        s0 += __shfl_xor_sync(0xffffffffu, s0, 2);
        s1 += __shfl_xor_sync(0xffffffffu, s1, 1);
        s1 += __shfl_xor_sync(0xffffffffu, s1, 2);
        if ((lane & 3) == 0) {
            int rl = wm * 64 + i * 16 + (lane >> 2);
            red[wn * 128 + rl] = s0;
            red[wn * 128 + rl + 8] = s1;
        }
    }
    __syncthreads();
    if (tid < 128) {
        float s = red[tid] + red[128 + tid] + red[256 + tid] + red[384 + tid];
        g_part[(size_t)blockIdx.x * N_CAND + mBase + tid] = s;
    }
}

__global__ void k_reduce(const float* __restrict__ b3, float* __restrict__ out) {
    int n = blockIdx.x * 256 + threadIdx.x;
    float s = b3[0];
    #pragma unroll
    for (int t = 0; t < 8; t++) s += g_part[(size_t)t * N_CAND + n];
    out[n] = s;
}

// ---------------- launch ----------------
extern "C" void kernel_launch(void* const* d_in, const int* in_sizes, int n_in,
                              void* d_out, int out_size) {
    const float* pf   = (const float*)d_in[0];
    const float* cand = (const float*)d_in[1];
    const float* W1   = (const float*)d_in[2];
    const float* b1   = (const float*)d_in[3];
    const float* W2   = (const float*)d_in[4];
    const float* b2   = (const float*)d_in[5];
    const float* W3   = (const float*)d_in[6];
    const float* b3   = (const float*)d_in[7];
    float* out = (float*)d_out;

    k_pool_b1<<<1, 256>>>(pf, W1, b1);                     // 1
    k_ptab<<<dim3(91, 2, 2), 256>>>(pf, W1);               // 2
    k_cand<<<(N_CAND * 16) / 256, 256>>>(cand);            // 3
    k_wcvt<<<dim3(32, 33), 256>>>(W2, W1);                 // 4

    cudaFuncSetAttribute(k_mma1, cudaFuncAttributeMaxDynamicSharedMemorySize, SMEM1);
    cudaFuncSetAttribute(k_mma2, cudaFuncAttributeMaxDynamicSharedMemorySize, SMEM2);

    dim3 g1(HID / 128, N_CAND / 128);                      // (8, 512)
    k_mma1<<<g1, 256, SMEM1>>>();                          // 5
    dim3 g2(HID / 128, N_CAND / 128);                      // (8, 512)
    k_mma2<<<g2, 256, SMEM2>>>(b2, W3);                    // 6  <- ncu -s5 lands here
    k_reduce<<<N_CAND / 256, 256>>>(b3, out);              // 7
}

// round 13
// speedup vs baseline: 1.2592x; 1.0617x over previous
#include <cuda_runtime.h>
#include <cuda_fp16.h>
#include <cstdint>

#define N_CAND 65536
#define HID 1024
#define C_CH 256
#define HW 361

// ---------------- scratch ----------------
__device__ float g_b1eff[HID];
__device__ __half g_P16[2 * HW * HID];       // [go/to][pos][1024] fp16; go-table includes b1eff
__device__ int   g_go[N_CAND], g_to[N_CAND];
__device__ __half g_c16[N_CAND * 64];        // cand feats fp16 [m][64]
__device__ __half g_Wc16[HID * 64];          // W1c^T [n][64]
__device__ __half g_W216[HID * HID];         // W2^T  [n][1024]
__device__ __half g_h116[(size_t)N_CAND * HID];
__device__ float g_part[8 * N_CAND];

// ---------------- helpers ----------------
__device__ __forceinline__ uint32_t smem_u32(const void* p) {
    uint32_t a;
    asm("{ .reg .u64 t; cvta.to.shared.u64 t, %1; cvt.u32.u64 %0, t; }" : "=r"(a) : "l"(p));
    return a;
}
__device__ __forceinline__ void cp16(uint32_t dst, const void* src) {
    asm volatile("cp.async.cg.shared.global [%0], [%1], 16;" :: "r"(dst), "l"(src));
}
__device__ __forceinline__ void cp_commit() { asm volatile("cp.async.commit_group;" ::: "memory"); }
template<int N> __device__ __forceinline__ void cp_wait() {
    asm volatile("cp.async.wait_group %0;" :: "n"(N) : "memory");
}
__device__ __forceinline__ void ldsm4(uint32_t* r, uint32_t a) {
    asm volatile("ldmatrix.sync.aligned.m8n8.x4.shared.b16 {%0,%1,%2,%3}, [%4];"
                 : "=r"(r[0]), "=r"(r[1]), "=r"(r[2]), "=r"(r[3]) : "r"(a));
}
__device__ __forceinline__ void ldsm2(uint32_t* r, uint32_t a) {
    asm volatile("ldmatrix.sync.aligned.m8n8.x2.shared.b16 {%0,%1}, [%2];"
                 : "=r"(r[0]), "=r"(r[1]) : "r"(a));
}
__device__ __forceinline__ void mmaf16(float* c, const uint32_t* a, const uint32_t* b) {
    asm volatile("mma.sync.aligned.m16n8k16.row.col.f32.f16.f16.f32 "
                 "{%0,%1,%2,%3}, {%4,%5,%6,%7}, {%8,%9}, {%0,%1,%2,%3};"
                 : "+f"(c[0]), "+f"(c[1]), "+f"(c[2]), "+f"(c[3])
                 : "r"(a[0]), "r"(a[1]), "r"(a[2]), "r"(a[3]), "r"(b[0]), "r"(b[1]));
}
__device__ __forceinline__ uint32_t pack2h(__half a, __half b) {
    return ((uint32_t)__half_as_ushort(b) << 16) | __half_as_ushort(a);
}

// ---------------- prep stage 1: b1eff (4 blocks; each recomputes gp) ----------------
__global__ void k_b1(const float* __restrict__ pf,
                     const float* __restrict__ W1, const float* __restrict__ b1) {
    __shared__ float sgp[C_CH];
    int tid = threadIdx.x;
    const float* row = pf + (size_t)tid * HW;
    float s = 0.f;
    for (int p = 0; p < HW; p++) s += row[p];
    sgp[tid] = s / 361.0f;
    __syncthreads();
    int j = blockIdx.x * 256 + tid;
    float acc = b1[j];
    #pragma unroll 4
    for (int c = 0; c < C_CH; c++)
        acc += sgp[c] * W1[(size_t)(512 + c) * HID + j];
    g_b1eff[j] = acc;
}

// ---------------- prep stage 2: fused ptab + cand + wcvt ----------------
#define NPTAB 364           // 91 * 2 * 2
#define NCANDB 4096         // N_CAND*16 float4s / 256
#define NWCVT 1056          // 32 * 33

__global__ void k_prep(const float* __restrict__ pf, const float* __restrict__ W1,
                       const float* __restrict__ W2, const float* __restrict__ cand) {
    int b = blockIdx.x;
    int tid = threadIdx.x;

    if (b < NPTAB) {
        // P tables (fp16): P[gy][pos][n]; gy==0 also folds in b1eff
        int p0 = (b % 91) * 4;
        int gy = (b / 91) & 1;
        int z  = b / 182;
        int n0 = z * 512 + tid * 2;
        __shared__ float fs[4][C_CH];
        for (int idx = tid; idx < 4 * C_CH; idx += 256) {
            int r = idx >> 8, k = idx & 255;
            fs[r][k] = (p0 + r < HW) ? pf[(size_t)k * HW + p0 + r] : 0.f;
        }
        __syncthreads();
        float2 acc[4];
        float2 bb = make_float2(0.f, 0.f);
        if (gy == 0) bb = *(const float2*)&g_b1eff[n0];
        #pragma unroll
        for (int r = 0; r < 4; r++) acc[r] = bb;
        const float* Wb = W1 + (size_t)gy * C_CH * HID;
        #pragma unroll 4
        for (int k = 0; k < C_CH; k++) {
            float2 w = *(const float2*)&Wb[(size_t)k * HID + n0];
            #pragma unroll
            for (int r = 0; r < 4; r++) {
                float f = fs[r][k];
                acc[r].x += f * w.x; acc[r].y += f * w.y;
            }
        }
        #pragma unroll
        for (int r = 0; r < 4; r++)
            if (p0 + r < HW)
                *(__half2*)&g_P16[((size_t)gy * HW + p0 + r) * HID + n0] =
                    __floats2half2_rn(acc[r].x, acc[r].y);
    } else if (b < NPTAB + NCANDB) {
        // cand -> fp16 + index decode
        int idx = (b - NPTAB) * 256 + tid;
        float4 v = ((const float4*)cand)[idx];
        ((uint2*)g_c16)[idx] = make_uint2(pack2h(__float2half(v.x), __float2half(v.y)),
                                          pack2h(__float2half(v.z), __float2half(v.w)));
        if ((idx & 15) == 1) {
            int i = idx >> 4;
            int gr = min(max((int)(v.y * 18.0f), 0), 18);
            int gc = min(max((int)(v.z * 18.0f), 0), 18);
            int tr = min(max((int)(v.w * 18.0f), 0), 18);
            float f8 = cand[(size_t)i * 64 + 8];
            int tc = min(max((int)(f8 * 18.0f), 0), 18);
            g_go[i] = gr * 19 + gc;
            g_to[i] = tr * 19 + tc;
        }
    } else {
        // W2^T fp16 (y<32) + Wc fp16 (y==32)
        int i = b - (NPTAB + NCANDB);
        int x = i & 31, y = i >> 5;
        if (y < 32) {
            __shared__ float tile[32][33];
            int kt = y * 32, nt = x * 32;
            int tx = tid & 31, ty = tid >> 5;
            for (int r = ty; r < 32; r += 8)
                tile[r][tx] = W2[(size_t)(kt + r) * HID + nt + tx];
            __syncthreads();
            for (int r = ty; r < 32; r += 8)
                g_W216[(size_t)(nt + r) * HID + kt + tx] = __float2half(tile[tx][r]);
        } else {
            for (int t = 0; t < 8; t++) {
                int idx = x * 2048 + t * 256 + tid;
                int n = idx >> 6, k = idx & 63;
                g_Wc16[idx] = __float2half(W1[(size_t)(768 + k) * HID + n]);
            }
        }
    }
}

// ---------------- GEMM1: CTA 128x128, 8 warps (2m x 4n), warp 64x32, K=64 ----------------
#define ROWB 80
#define G1_OA 0
#define G1_OB 10240
#define G1_STRIDE 20480
#define SMEM1 (2 * G1_STRIDE)

__global__ __launch_bounds__(256, 2)
void k_mma1() {
    extern __shared__ char smem[];
    const uint32_t sb = smem_u32(smem);
    const int tid = threadIdx.x;
    const int lane = tid & 31, wid = tid >> 5;
    const int wm = wid >> 2, wn = wid & 3;
    const int mBase = blockIdx.y * 128;
    const int nBase = blockIdx.x * 128;

    const int lrow = tid >> 1;
    const int lc = (tid & 1) * 2;
    const __half* aP = g_c16 + (size_t)(mBase + lrow) * 64 + lc * 8;
    const __half* bP = g_Wc16 + (size_t)(nBase + lrow) * 64 + lc * 8;
    const uint32_t sA = lrow * ROWB + lc * 16;

    auto load_chunk = [&](int chunk, int buf) {
        uint32_t st = sb + buf * G1_STRIDE;
        int k0 = chunk * 32;
        cp16(st + G1_OA + sA,      aP + k0);
        cp16(st + G1_OA + sA + 16, aP + k0 + 8);
        cp16(st + G1_OB + sA,      bP + k0);
        cp16(st + G1_OB + sA + 16, bP + k0 + 8);
        cp_commit();
    };
    load_chunk(0, 0);
    load_chunk(1, 1);

    float acc[4][4][4];
    #pragma unroll
    for (int i = 0; i < 4; i++)
        #pragma unroll
        for (int j = 0; j < 4; j++)
            #pragma unroll
            for (int q = 0; q < 4; q++) acc[i][j][q] = 0.f;

    const uint32_t aOff = (uint32_t)((wm * 64 + (lane & 15)) * ROWB + (lane >> 4) * 16);
    const uint32_t bOff = (uint32_t)((wn * 32 + (lane & 7)) * ROWB + ((lane >> 3) & 1) * 16);

    #pragma unroll
    for (int c = 0; c < 2; c++) {
        if (c == 0) cp_wait<1>(); else cp_wait<0>();
        __syncthreads();
        uint32_t st = sb + c * G1_STRIDE;
        #pragma unroll
        for (int kk = 0; kk < 2; kk++) {
            uint32_t a[4][4], b[4][2];
            #pragma unroll
            for (int i = 0; i < 4; i++)
                ldsm4(a[i], st + G1_OA + aOff + i * (16 * ROWB) + kk * 32);
            #pragma unroll
            for (int j = 0; j < 4; j++)
                ldsm2(b[j], st + G1_OB + bOff + j * (8 * ROWB) + kk * 32);
            #pragma unroll
            for (int i = 0; i < 4; i++)
                #pragma unroll
                for (int j = 0; j < 4; j++)
                    mmaf16(acc[i][j], a[i], b[j]);
        }
        __syncthreads();
    }

    int* sgo = (int*)smem;
    int* sto = (int*)(smem + 512);
    if (tid < 128) { sgo[tid] = g_go[mBase + tid]; sto[tid] = g_to[mBase + tid]; }
    __syncthreads();
    #pragma unroll
    for (int i = 0; i < 4; i++) {
        #pragma unroll
        for (int rr = 0; rr < 2; rr++) {
            int rl = wm * 64 + i * 16 + rr * 8 + (lane >> 2);
            size_t row = (size_t)(mBase + rl);
            const __half* pg = g_P16 + (size_t)sgo[rl] * HID;           // includes b1eff
            const __half* pt = g_P16 + (size_t)(HW + sto[rl]) * HID;
            #pragma unroll
            for (int j = 0; j < 4; j++) {
                int n = nBase + wn * 32 + j * 8 + 2 * (lane & 3);
                float2 pgv = __half22float2(*(const __half2*)&pg[n]);
                float2 ptv = __half22float2(*(const __half2*)&pt[n]);
                float v0 = acc[i][j][rr * 2 + 0] + pgv.x + ptv.x;
                float v1 = acc[i][j][rr * 2 + 1] + pgv.y + ptv.y;
                v0 = fmaxf(v0, 0.f); v1 = fmaxf(v1, 0.f);
                *(uint32_t*)&g_h116[row * HID + n] = pack2h(__float2half(v0), __float2half(v1));
            }
        }
    }
}

// ---------------- GEMM2: CTA 128x128, 8 warps, warp 64x32, 4-buffer pipeline ----------------
#define G2_OA 0
#define G2_OB 10240
#define G2_STRIDE 20480
#define SMEM2 (4 * G2_STRIDE)

__global__ __launch_bounds__(256, 2)
void k_mma2(const float* __restrict__ b2, const float* __restrict__ w3) {
    extern __shared__ char smem[];
    const uint32_t sb = smem_u32(smem);
    const int tid = threadIdx.x;
    const int lane = tid & 31, wid = tid >> 5;
    const int wm = wid >> 2, wn = wid & 3;
    const int mBase = blockIdx.y * 128;
    const int nBase = blockIdx.x * 128;
    const int NC = 32;

    const int lrow = tid >> 1;
    const int lc = (tid & 1) * 2;
    const __half* aP = g_h116 + (size_t)(mBase + lrow) * HID + lc * 8;
    const __half* bP = g_W216 + (size_t)(nBase + lrow) * HID + lc * 8;
    const uint32_t sA = lrow * ROWB + lc * 16;

    auto load_chunk = [&](int chunk, int buf) {
        uint32_t st = sb + buf * G2_STRIDE;
        int k0 = chunk * 32;
        cp16(st + G2_OA + sA,      aP + k0);
        cp16(st + G2_OA + sA + 16, aP + k0 + 8);
        cp16(st + G2_OB + sA,      bP + k0);
        cp16(st + G2_OB + sA + 16, bP + k0 + 8);
        cp_commit();
    };
    load_chunk(0, 0);
    load_chunk(1, 1);
    load_chunk(2, 2);

    float acc[4][4][4];
    #pragma unroll
    for (int i = 0; i < 4; i++)
        #pragma unroll
        for (int j = 0; j < 4; j++)
            #pragma unroll
            for (int q = 0; q < 4; q++) acc[i][j][q] = 0.f;

    const uint32_t aOff = (uint32_t)((wm * 64 + (lane & 15)) * ROWB + (lane >> 4) * 16);
    // B via ldsm.x4: lanes0-7 -> rows n0..7 (k-lo), 8-15 -> k-hi, 16-23 -> n8..15, 24-31 -> k-hi
    const uint32_t bOff = (uint32_t)((wn * 32 + (lane & 7) + ((lane >> 4) << 3)) * ROWB
                                     + ((lane >> 3) & 1) * 16);

    int buf = 0;
    for (int c = 0; c < NC; c++) {
        if (NC - 1 - c >= 2) cp_wait<2>();
        else if (NC - 1 - c == 1) cp_wait<1>();
        else cp_wait<0>();
        __syncthreads();
        // prefetch c+3 into slot (c+3)&3 == (c-1)&3: its chunk c-1 reads all
        // completed before the sync above -> WAR-safe, no second sync needed.
        if (c + 3 < NC) load_chunk(c + 3, (c + 3) & 3);

        uint32_t st = sb + buf * G2_STRIDE;
        #pragma unroll
        for (int kk = 0; kk < 2; kk++) {
            uint32_t a[4][4], b[2][4];
            #pragma unroll
            for (int i = 0; i < 4; i++)
                ldsm4(a[i], st + G2_OA + aOff + i * (16 * ROWB) + kk * 32);
            #pragma unroll
            for (int j2 = 0; j2 < 2; j2++)
                ldsm4(b[j2], st + G2_OB + bOff + j2 * (16 * ROWB) + kk * 32);
            #pragma unroll
            for (int i = 0; i < 4; i++)
                #pragma unroll
                for (int j2 = 0; j2 < 2; j2++) {
                    mmaf16(acc[i][j2 * 2],     a[i], &b[j2][0]);
                    mmaf16(acc[i][j2 * 2 + 1], a[i], &b[j2][2]);
                }
        }
        buf = (buf + 1) & 3;
    }
    __syncthreads();

    float* red = (float*)smem;   // [4][128]
    #pragma unroll
    for (int i = 0; i < 4; i++) {
        float s0 = 0.f, s1 = 0.f;
        #pragma unroll
        for (int j = 0; j < 4; j++) {
            int n = nBase + wn * 32 + j * 8 + 2 * (lane & 3);
            float2 bb = *(const float2*)&b2[n];
            float2 ww = *(const float2*)&w3[n];
            s0 += fmaxf(acc[i][j][0] + bb.x, 0.f) * ww.x + fmaxf(acc[i][j][1] + bb.y, 0.f) * ww.y;
            s1 += fmaxf(acc[i][j][2] + bb.x, 0.f) * ww.x + fmaxf(acc[i][j][3] + bb.y, 0.f) * ww.y;
        }
        s0 += __shfl_xor_sync(0xffffffffu, s0, 1);
        s0 += __shfl_xor_sync(0xffffffffu, s0, 2);
        s1 += __shfl_xor_sync(0xffffffffu, s1, 1);
        s1 += __shfl_xor_sync(0xffffffffu, s1, 2);
        if ((lane & 3) == 0) {
            int rl = wm * 64 + i * 16 + (lane >> 2);
            red[wn * 128 + rl] = s0;
            red[wn * 128 + rl + 8] = s1;
        }
    }
    __syncthreads();
    if (tid < 128) {
        float s = red[tid] + red[128 + tid] + red[256 + tid] + red[384 + tid];
        g_part[(size_t)blockIdx.x * N_CAND + mBase + tid] = s;
    }
}

__global__ void k_reduce(const float* __restrict__ b3, float* __restrict__ out) {
    int n = blockIdx.x * 256 + threadIdx.x;
    float s = b3[0];
    #pragma unroll
    for (int t = 0; t < 8; t++) s += g_part[(size_t)t * N_CAND + n];
    out[n] = s;
}

// ---------------- launch ----------------
extern "C" void kernel_launch(void* const* d_in, const int* in_sizes, int n_in,
                              void* d_out, int out_size) {
    const float* pf   = (const float*)d_in[0];
    const float* cand = (const float*)d_in[1];
    const float* W1   = (const float*)d_in[2];
    const float* b1   = (const float*)d_in[3];
    const float* W2   = (const float*)d_in[4];
    const float* b2   = (const float*)d_in[5];
    const float* W3   = (const float*)d_in[6];
    const float* b3   = (const float*)d_in[7];
    float* out = (float*)d_out;

    k_b1<<<4, 256>>>(pf, W1, b1);                                   // 1
    k_prep<<<NPTAB + NCANDB + NWCVT, 256>>>(pf, W1, W2, cand);      // 2

    cudaFuncSetAttribute(k_mma1, cudaFuncAttributeMaxDynamicSharedMemorySize, SMEM1);
    cudaFuncSetAttribute(k_mma2, cudaFuncAttributeMaxDynamicSharedMemorySize, SMEM2);

    dim3 g1(HID / 128, N_CAND / 128);                               // (8, 512)
    k_mma1<<<g1, 256, SMEM1>>>();                                   // 3
    dim3 g2(HID / 128, N_CAND / 128);                               // (8, 512)
    k_mma2<<<g2, 256, SMEM2>>>(b2, W3);                             // 4
    k_reduce<<<N_CAND / 256, 256>>>(b3, out);                       // 5
}